// round 1
// baseline (speedup 1.0000x reference)
#include <cuda_runtime.h>
#include <math_constants.h>
#include <stdint.h>

#define B  32
#define N  8192
#define K  128
#define PS 32

#define BINS 2048
#define CAP  512

// Scratch (allocation-free rule: __device__ globals)
__device__ int   g_fps_idx[B * K];
__device__ float g_centers[B * K * 3];
__device__ int   g_knn[B * K * PS];

// ---------------------------------------------------------------------------
// FPS: one block per batch, 1024 threads, 8 points/thread in registers.
// Matches reference semantics: start index 0, mind=inf, argmax ties -> lowest idx.
// ---------------------------------------------------------------------------
extern "C" __global__ void __launch_bounds__(1024, 1)
fps_kernel(const float* __restrict__ points) {
    extern __shared__ float pts[];  // raw copy of [N][3] = 24576 floats (96KB)
    __shared__ float s_bv[32];
    __shared__ int   s_bi[32];
    __shared__ int   s_cur;

    const int b = blockIdx.x;
    const int t = threadIdx.x;
    const float* gp = points + (size_t)b * N * 3;

    for (int i = t; i < N * 3; i += 1024) pts[i] = gp[i];
    __syncthreads();

    float px[8], py[8], pz[8], md[8];
#pragma unroll
    for (int j = 0; j < 8; j++) {
        int n = t + j * 1024;
        px[j] = pts[3 * n + 0];
        py[j] = pts[3 * n + 1];
        pz[j] = pts[3 * n + 2];
        md[j] = CUDART_INF_F;
    }

    int cur = 0;
    const int lane = t & 31, w = t >> 5;
    for (int k = 0; k < K; k++) {
        float cx = pts[3 * cur + 0];
        float cy = pts[3 * cur + 1];
        float cz = pts[3 * cur + 2];
        if (t == 0) {
            g_fps_idx[b * K + k] = cur;
            g_centers[(b * K + k) * 3 + 0] = cx;
            g_centers[(b * K + k) * 3 + 1] = cy;
            g_centers[(b * K + k) * 3 + 2] = cz;
        }
        float bv = -1.0f;
        int   bi = 0;
#pragma unroll
        for (int j = 0; j < 8; j++) {
            float dx = px[j] - cx, dy = py[j] - cy, dz = pz[j] - cz;
            float d = dx * dx + dy * dy + dz * dz;
            md[j] = fminf(md[j], d);
            // j ascending => strict '>' keeps lowest global index on ties
            if (md[j] > bv) { bv = md[j]; bi = t + j * 1024; }
        }
        // warp argmax (value desc, index asc on ties)
#pragma unroll
        for (int off = 16; off; off >>= 1) {
            float ov = __shfl_down_sync(0xffffffffu, bv, off);
            int   oi = __shfl_down_sync(0xffffffffu, bi, off);
            if (ov > bv || (ov == bv && oi < bi)) { bv = ov; bi = oi; }
        }
        if (lane == 0) { s_bv[w] = bv; s_bi[w] = bi; }
        __syncthreads();
        if (w == 0) {
            bv = s_bv[lane];
            bi = s_bi[lane];
#pragma unroll
            for (int off = 16; off; off >>= 1) {
                float ov = __shfl_down_sync(0xffffffffu, bv, off);
                int   oi = __shfl_down_sync(0xffffffffu, bi, off);
                if (ov > bv || (ov == bv && oi < bi)) { bv = ov; bi = oi; }
            }
            if (lane == 0) s_cur = bi;
        }
        __syncthreads();
        cur = s_cur;
    }
}

// ---------------------------------------------------------------------------
// KNN: one block per (b,k) row, 256 threads. Histogram radix-select on
// sign-fixed float keys, then O(C^2) stable rank sort of candidates.
// d2 = (cc + pp) - 2*dot, identical algebraic form to the reference.
// ---------------------------------------------------------------------------
__device__ __forceinline__ unsigned f2key(float f) {
    unsigned bits = __float_as_uint(f);
    return (bits & 0x80000000u) ? ~bits : (bits | 0x80000000u);
}

extern "C" __global__ void __launch_bounds__(256)
knn_kernel(const float* __restrict__ points) {
    __shared__ float    s_d2[N];          // 32 KB
    __shared__ unsigned s_hist[BINS];     // 8 KB
    __shared__ int      s_cidx[CAP];      // 2 KB
    __shared__ unsigned s_ckey[CAP];      // 2 KB
    __shared__ unsigned s_wsum[8];
    __shared__ int      s_T;
    __shared__ int      s_cnt;
    __shared__ unsigned s_fk[8];
    __shared__ int      s_fi[8];

    const int row = blockIdx.x;     // b*K + k
    const int b   = row >> 7;
    const int t   = threadIdx.x;
    const float* gp = points + (size_t)b * N * 3;

    const float cx = g_centers[row * 3 + 0];
    const float cy = g_centers[row * 3 + 1];
    const float cz = g_centers[row * 3 + 2];
    const float cc = cx * cx + cy * cy + cz * cz;

    for (int i = t; i < BINS; i += 256) s_hist[i] = 0u;
    if (t == 0) s_cnt = 0;
    __syncthreads();

#pragma unroll
    for (int j = 0; j < N / 256; j++) {
        int n = t + j * 256;
        float px = gp[3 * n + 0], py = gp[3 * n + 1], pz = gp[3 * n + 2];
        float pp  = px * px + py * py + pz * pz;
        float dot = cx * px + cy * py + cz * pz;
        float d2  = (cc + pp) - 2.0f * dot;
        s_d2[n] = d2;
        atomicAdd(&s_hist[f2key(d2) >> 21], 1u);
    }
    __syncthreads();

    // find threshold bin T: first bin where cumulative count >= PS
    unsigned c8[8], seg = 0;
#pragma unroll
    for (int i = 0; i < 8; i++) { c8[i] = s_hist[t * 8 + i]; seg += c8[i]; }
    unsigned pre = seg;
    const int lane = t & 31, w = t >> 5;
#pragma unroll
    for (int off = 1; off < 32; off <<= 1) {
        unsigned v = __shfl_up_sync(0xffffffffu, pre, off);
        if (lane >= off) pre += v;
    }
    if (lane == 31) s_wsum[w] = pre;
    __syncthreads();
    unsigned wbase = 0;
    for (int i = 0; i < w; i++) wbase += s_wsum[i];
    unsigned excl = wbase + pre - seg;
    if (excl < PS && excl + seg >= PS) {
        unsigned cum = excl;
        int Tb = -1;
#pragma unroll
        for (int i = 0; i < 8; i++) {
            cum += c8[i];
            if (Tb < 0 && cum >= PS) Tb = t * 8 + i;
        }
        s_T = Tb;
    }
    __syncthreads();
    const int T = s_T;

    // collect candidates: all points in bins <= T
#pragma unroll
    for (int j = 0; j < N / 256; j++) {
        int n = t + j * 256;
        unsigned key = f2key(s_d2[n]);
        if ((int)(key >> 21) <= T) {
            int pos = atomicAdd(&s_cnt, 1);
            if (pos < CAP) { s_cidx[pos] = n; s_ckey[pos] = key; }
        }
    }
    __syncthreads();
    const int C = s_cnt;
    int* out = &g_knn[row * PS];

    if (C <= CAP) {
        // stable rank sort: rank = #{(key,idx) strictly smaller}
        for (int j = t; j < C; j += 256) {
            unsigned kj = s_ckey[j];
            int      nj = s_cidx[j];
            int r = 0;
            for (int m = 0; m < C; m++) {
                unsigned km = s_ckey[m];
                r += (km < kj) || (km == kj && s_cidx[m] < nj);
            }
            if (r < PS) out[r] = nj;
        }
    } else {
        // rare fallback: PS sequential arg-mins over s_d2
        for (int sel = 0; sel < PS; sel++) {
            unsigned bk = 0xffffffffu;
            int      bi = 0x7fffffff;
#pragma unroll
            for (int j = 0; j < N / 256; j++) {
                int n = t + j * 256;
                unsigned key = f2key(s_d2[n]);
                if (key < bk || (key == bk && n < bi)) { bk = key; bi = n; }
            }
#pragma unroll
            for (int off = 16; off; off >>= 1) {
                unsigned ok = __shfl_down_sync(0xffffffffu, bk, off);
                int      oi = __shfl_down_sync(0xffffffffu, bi, off);
                if (ok < bk || (ok == bk && oi < bi)) { bk = ok; bi = oi; }
            }
            if (lane == 0) { s_fk[w] = bk; s_fi[w] = bi; }
            __syncthreads();
            if (t == 0) {
                unsigned bbk = s_fk[0];
                int      bbi = s_fi[0];
                for (int i = 1; i < 8; i++)
                    if (s_fk[i] < bbk || (s_fk[i] == bbk && s_fi[i] < bbi)) {
                        bbk = s_fk[i]; bbi = s_fi[i];
                    }
                out[sel] = bbi;
                s_d2[bbi] = CUDART_INF_F;
            }
            __syncthreads();
        }
    }
}

// ---------------------------------------------------------------------------
// Epilogues — handle both plausible output layouts.
// ---------------------------------------------------------------------------
extern "C" __global__ void epilogue_i32(int* __restrict__ out, int out_size) {
    int i = blockIdx.x * 256 + threadIdx.x;
    if (i < out_size && i < B * K * PS) out[i] = g_knn[i];
}

extern "C" __global__ void epilogue_f32(float* __restrict__ out, int out_size) {
    int i = blockIdx.x * 256 + threadIdx.x;
    if (i >= out_size) return;
    if (i < B * K * PS) {
        out[i] = (float)g_knn[i];
    } else if (i < B * K * PS + B * K * 3) {
        out[i] = g_centers[i - B * K * PS];
    }
}

// ---------------------------------------------------------------------------
extern "C" void kernel_launch(void* const* d_in, const int* in_sizes, int n_in,
                              void* d_out, int out_size) {
    (void)in_sizes; (void)n_in;
    const float* points = (const float*)d_in[0];

    cudaFuncSetAttribute(fps_kernel,
                         cudaFuncAttributeMaxDynamicSharedMemorySize,
                         N * 3 * (int)sizeof(float));

    fps_kernel<<<B, 1024, N * 3 * sizeof(float)>>>(points);
    knn_kernel<<<B * K, 256>>>(points);

    if (out_size == B * K * PS) {
        // idx-only output, int32
        int total = B * K * PS;
        epilogue_i32<<<(total + 255) / 256, 256>>>((int*)d_out, out_size);
    } else {
        // concatenated (idx, centers) as float32
        int total = B * K * PS + B * K * 3;
        int n = total < out_size ? out_size : total;
        epilogue_f32<<<(n + 255) / 256, 256>>>((float*)d_out, out_size);
    }
}

// round 2
// speedup vs baseline: 1.0792x; 1.0792x over previous
#include <cuda_runtime.h>
#include <math_constants.h>
#include <stdint.h>

#define B  32
#define N  8192
#define K  128
#define PS 32

#define BINS 2048
#define CAP  512
#define RPC  2          // KNN rows per CTA

typedef unsigned long long u64;

// Scratch (allocation-free rule: __device__ globals)
__device__ int   g_fps_idx[B * K];
__device__ float g_centers[B * K * 3];
__device__ int   g_knn[B * K * PS];

// ---------------------------------------------------------------------------
// f32x2 packed helpers (each = ONE fma-pipe instruction doing 2 IEEE .rn ops;
// bit-identical to the scalar versions)
// ---------------------------------------------------------------------------
__device__ __forceinline__ u64 pack2(float lo, float hi) {
    u64 r; asm("mov.b64 %0, {%1, %2};" : "=l"(r) : "f"(lo), "f"(hi)); return r;
}
__device__ __forceinline__ float2 unpack2(u64 v) {
    float2 f; asm("mov.b64 {%0, %1}, %2;" : "=f"(f.x), "=f"(f.y) : "l"(v)); return f;
}
__device__ __forceinline__ u64 add2(u64 a, u64 b) {
    u64 d; asm("add.rn.f32x2 %0, %1, %2;" : "=l"(d) : "l"(a), "l"(b)); return d;
}
__device__ __forceinline__ u64 mul2(u64 a, u64 b) {
    u64 d; asm("mul.rn.f32x2 %0, %1, %2;" : "=l"(d) : "l"(a), "l"(b)); return d;
}
__device__ __forceinline__ u64 fma2(u64 a, u64 b, u64 c) {
    u64 d; asm("fma.rn.f32x2 %0, %1, %2, %3;" : "=l"(d) : "l"(a), "l"(b), "l"(c)); return d;
}

// ---------------------------------------------------------------------------
// FPS: one block per batch, 1024 threads, 8 points/thread.
// Distance update packed 2-wide; argmax via value REDUX + smem atomicMax,
// then equality search + atomicMin (exactly reproduces lowest-index ties).
// ---------------------------------------------------------------------------
extern "C" __global__ void __launch_bounds__(1024, 1)
fps_kernel(const float* __restrict__ points) {
    extern __shared__ float pts[];      // [N*3] = 96KB
    __shared__ unsigned s_maxb[K];
    __shared__ int      s_idx[K];

    const int b = blockIdx.x;
    const int t = threadIdx.x;
    const float* gp = points + (size_t)b * N * 3;

    for (int i = t; i < N * 3; i += 1024) pts[i] = gp[i];
    if (t < K) { s_maxb[t] = 0u; s_idx[t] = 0x7fffffff; }
    __syncthreads();

    // slot s handles point index t + s*1024; pairs (2j, 2j+1) packed.
    u64 px2[4], py2[4], pz2[4];
    float md[8];
#pragma unroll
    for (int j = 0; j < 4; j++) {
        int nlo = t + (2 * j) * 1024;
        int nhi = t + (2 * j + 1) * 1024;
        px2[j] = pack2(pts[3 * nlo + 0], pts[3 * nhi + 0]);
        py2[j] = pack2(pts[3 * nlo + 1], pts[3 * nhi + 1]);
        pz2[j] = pack2(pts[3 * nlo + 2], pts[3 * nhi + 2]);
        md[2 * j] = CUDART_INF_F; md[2 * j + 1] = CUDART_INF_F;
    }

    int cur = 0;
    const int lane = t & 31;
    for (int k = 0; k < K; k++) {
        float cx = pts[3 * cur + 0];
        float cy = pts[3 * cur + 1];
        float cz = pts[3 * cur + 2];
        if (t == 0) {
            g_fps_idx[b * K + k] = cur;
            g_centers[(b * K + k) * 3 + 0] = cx;
            g_centers[(b * K + k) * 3 + 1] = cy;
            g_centers[(b * K + k) * 3 + 2] = cz;
        }
        // px - cx computed as px + (-cx): exact.
        u64 nc2x = pack2(-cx, -cx);
        u64 nc2y = pack2(-cy, -cy);
        u64 nc2z = pack2(-cz, -cz);
#pragma unroll
        for (int j = 0; j < 4; j++) {
            u64 dx = add2(px2[j], nc2x);
            u64 dy = add2(py2[j], nc2y);
            u64 dz = add2(pz2[j], nc2z);
            u64 d  = mul2(dx, dx);
            d = fma2(dy, dy, d);
            d = fma2(dz, dz, d);
            float2 f = unpack2(d);
            md[2 * j]     = fminf(md[2 * j],     f.x);
            md[2 * j + 1] = fminf(md[2 * j + 1], f.y);
        }
        // thread max (value only)
        float tv = fmaxf(fmaxf(fmaxf(md[0], md[1]), fmaxf(md[2], md[3])),
                         fmaxf(fmaxf(md[4], md[5]), fmaxf(md[6], md[7])));
        // nonneg float bits are order-preserving as uint
        unsigned wv = __reduce_max_sync(0xffffffffu, __float_as_uint(tv));
        if (lane == 0) atomicMax(&s_maxb[k], wv);
        __syncthreads();
        const unsigned mb = s_maxb[k];
        // lowest index achieving the max (exact bit equality)
        int li = 0x7fffffff;
#pragma unroll
        for (int s = 0; s < 8; s++) {
            if (__float_as_uint(md[s]) == mb) li = min(li, t + s * 1024);
        }
        if (li != 0x7fffffff) atomicMin(&s_idx[k], li);
        __syncthreads();
        cur = s_idx[k];
    }
}

// ---------------------------------------------------------------------------
// KNN: RPC=2 rows per CTA (same batch -> shared point loads; halves L2
// traffic). Histogram radix-select + stable rank sort, exactly as before.
// ---------------------------------------------------------------------------
__device__ __forceinline__ unsigned f2key(float f) {
    unsigned bits = __float_as_uint(f);
    return (bits & 0x80000000u) ? ~bits : (bits | 0x80000000u);
}

extern "C" __global__ void __launch_bounds__(256)
knn_kernel(const float* __restrict__ points) {
    extern __shared__ char sm[];
    float*    s_d2   = (float*)sm;                               // RPC*N   (64KB)
    unsigned* s_hist = (unsigned*)(sm + RPC * N * 4);            // RPC*BINS(16KB)
    int*      s_cidx = (int*)(sm + RPC * N * 4 + RPC * BINS * 4);          // RPC*CAP
    unsigned* s_ckey = (unsigned*)(sm + RPC * N * 4 + RPC * BINS * 4 + RPC * CAP * 4);

    __shared__ unsigned s_wsum[8];
    __shared__ int      s_T[RPC];
    __shared__ int      s_cnt[RPC];
    __shared__ unsigned s_fk[8];
    __shared__ int      s_fi[8];

    const int row0 = blockIdx.x * RPC;   // b*K + k (RPC consecutive, same batch)
    const int b    = row0 >> 7;
    const int t    = threadIdx.x;
    const int lane = t & 31, w = t >> 5;
    const float* gp = points + (size_t)b * N * 3;

    float cx[RPC], cy[RPC], cz[RPC], cc[RPC];
#pragma unroll
    for (int r = 0; r < RPC; r++) {
        cx[r] = g_centers[(row0 + r) * 3 + 0];
        cy[r] = g_centers[(row0 + r) * 3 + 1];
        cz[r] = g_centers[(row0 + r) * 3 + 2];
        cc[r] = cx[r] * cx[r] + cy[r] * cy[r] + cz[r] * cz[r];
    }

    for (int i = t; i < RPC * BINS; i += 256) s_hist[i] = 0u;
    if (t < RPC) s_cnt[t] = 0;
    __syncthreads();

#pragma unroll
    for (int j = 0; j < N / 256; j++) {
        int n = t + j * 256;
        float px = gp[3 * n + 0], py = gp[3 * n + 1], pz = gp[3 * n + 2];
        float pp = px * px + py * py + pz * pz;
#pragma unroll
        for (int r = 0; r < RPC; r++) {
            float dot = cx[r] * px + cy[r] * py + cz[r] * pz;
            float d2  = (cc[r] + pp) - 2.0f * dot;
            s_d2[r * N + n] = d2;
            atomicAdd(&s_hist[r * BINS + (f2key(d2) >> 21)], 1u);
        }
    }
    __syncthreads();

    for (int r = 0; r < RPC; r++) {
        const float*    d2row = &s_d2[r * N];
        const unsigned* hist  = &s_hist[r * BINS];
        int*      cidx = &s_cidx[r * CAP];
        unsigned* ckey = &s_ckey[r * CAP];
        int*      out  = &g_knn[(row0 + r) * PS];

        // threshold bin T: first bin where cumulative count >= PS
        unsigned c8[8], seg = 0;
#pragma unroll
        for (int i = 0; i < 8; i++) { c8[i] = hist[t * 8 + i]; seg += c8[i]; }
        unsigned pre = seg;
#pragma unroll
        for (int off = 1; off < 32; off <<= 1) {
            unsigned v = __shfl_up_sync(0xffffffffu, pre, off);
            if (lane >= off) pre += v;
        }
        if (lane == 31) s_wsum[w] = pre;
        __syncthreads();
        unsigned wbase = 0;
        for (int i = 0; i < w; i++) wbase += s_wsum[i];
        unsigned excl = wbase + pre - seg;
        if (excl < PS && excl + seg >= PS) {
            unsigned cum = excl;
            int Tb = -1;
#pragma unroll
            for (int i = 0; i < 8; i++) {
                cum += c8[i];
                if (Tb < 0 && cum >= PS) Tb = t * 8 + i;
            }
            s_T[r] = Tb;
        }
        __syncthreads();
        const int T = s_T[r];

        // collect candidates (bins <= T)
#pragma unroll
        for (int j = 0; j < N / 256; j++) {
            int n = t + j * 256;
            unsigned key = f2key(d2row[n]);
            if ((int)(key >> 21) <= T) {
                int pos = atomicAdd(&s_cnt[r], 1);
                if (pos < CAP) { cidx[pos] = n; ckey[pos] = key; }
            }
        }
        __syncthreads();
        const int C = s_cnt[r];

        if (C <= CAP) {
            // stable rank sort
            for (int j = t; j < C; j += 256) {
                unsigned kj = ckey[j];
                int      nj = cidx[j];
                int rk = 0;
                for (int m = 0; m < C; m++) {
                    unsigned km = ckey[m];
                    rk += (km < kj) || (km == kj && cidx[m] < nj);
                }
                if (rk < PS) out[rk] = nj;
            }
        } else {
            // rare fallback: PS sequential arg-mins (destroys d2row; it is
            // no longer needed for this row afterwards)
            float* d2m = &s_d2[r * N];
            for (int sel = 0; sel < PS; sel++) {
                unsigned bk = 0xffffffffu;
                int      bi = 0x7fffffff;
#pragma unroll
                for (int j = 0; j < N / 256; j++) {
                    int n = t + j * 256;
                    unsigned key = f2key(d2m[n]);
                    if (key < bk || (key == bk && n < bi)) { bk = key; bi = n; }
                }
#pragma unroll
                for (int off = 16; off; off >>= 1) {
                    unsigned ok = __shfl_down_sync(0xffffffffu, bk, off);
                    int      oi = __shfl_down_sync(0xffffffffu, bi, off);
                    if (ok < bk || (ok == bk && oi < bi)) { bk = ok; bi = oi; }
                }
                if (lane == 0) { s_fk[w] = bk; s_fi[w] = bi; }
                __syncthreads();
                if (t == 0) {
                    unsigned bbk = s_fk[0];
                    int      bbi = s_fi[0];
                    for (int i = 1; i < 8; i++)
                        if (s_fk[i] < bbk || (s_fk[i] == bbk && s_fi[i] < bbi)) {
                            bbk = s_fk[i]; bbi = s_fi[i];
                        }
                    out[sel] = bbi;
                    d2m[bbi] = CUDART_INF_F;
                }
                __syncthreads();
            }
        }
        __syncthreads();
    }
}

// ---------------------------------------------------------------------------
// Epilogues — handle both plausible output layouts.
// ---------------------------------------------------------------------------
extern "C" __global__ void epilogue_i32(int* __restrict__ out, int out_size) {
    int i = blockIdx.x * 256 + threadIdx.x;
    if (i < out_size && i < B * K * PS) out[i] = g_knn[i];
}

extern "C" __global__ void epilogue_f32(float* __restrict__ out, int out_size) {
    int i = blockIdx.x * 256 + threadIdx.x;
    if (i >= out_size) return;
    if (i < B * K * PS) {
        out[i] = (float)g_knn[i];
    } else if (i < B * K * PS + B * K * 3) {
        out[i] = g_centers[i - B * K * PS];
    }
}

// ---------------------------------------------------------------------------
extern "C" void kernel_launch(void* const* d_in, const int* in_sizes, int n_in,
                              void* d_out, int out_size) {
    (void)in_sizes; (void)n_in;
    const float* points = (const float*)d_in[0];

    const int fps_smem = N * 3 * (int)sizeof(float);
    const int knn_smem = RPC * (N * 4 + BINS * 4 + CAP * 4 + CAP * 4);

    cudaFuncSetAttribute(fps_kernel,
                         cudaFuncAttributeMaxDynamicSharedMemorySize, fps_smem);
    cudaFuncSetAttribute(knn_kernel,
                         cudaFuncAttributeMaxDynamicSharedMemorySize, knn_smem);

    fps_kernel<<<B, 1024, fps_smem>>>(points);
    knn_kernel<<<B * K / RPC, 256, knn_smem>>>(points);

    if (out_size == B * K * PS) {
        int total = B * K * PS;
        epilogue_i32<<<(total + 255) / 256, 256>>>((int*)d_out, out_size);
    } else {
        int total = B * K * PS + B * K * 3;
        int n = total < out_size ? out_size : total;
        epilogue_f32<<<(n + 255) / 256, 256>>>((float*)d_out, out_size);
    }
}